// round 1
// baseline (speedup 1.0000x reference)
#include <cuda_runtime.h>
#include <cstdint>

// ---------------------------------------------------------------------------
// Problem constants
// ---------------------------------------------------------------------------
#define D_MODEL   2048
#define N_HEADS   16
#define D_HEAD    128
#define HEAD_V    256
#define KEY_DIM   2048
#define VALUE_DIM 4096
#define NPROJ     12320     // 2*KEY_DIM + 2*VALUE_DIM + 2*N_HEADS
#define CONV_CH   8192      // 2*KEY_DIM + VALUE_DIM
#define BATCH     2
#define SEQ       2048
#define MROWS     (BATCH*SEQ)          // 4096
#define GATE_OFF  8192
#define BCOL_OFF  12288
#define ACOL_OFF  12304

// ---------------------------------------------------------------------------
// Scratch (static device globals -- no allocation allowed)
// ---------------------------------------------------------------------------
__device__ float g_proj[(size_t)MROWS * NPROJ];    // 4096 x 12320
__device__ float g_qb[(size_t)MROWS * KEY_DIM];    // conv+silu+l2norm q
__device__ float g_kb[(size_t)MROWS * KEY_DIM];    // conv+silu+l2norm k
__device__ float g_vb[(size_t)MROWS * VALUE_DIM];  // conv+silu v
__device__ float g_eg[(size_t)MROWS * N_HEADS];    // exp(g)
__device__ float g_beta[(size_t)MROWS * N_HEADS];  // sigmoid(b)

// ---------------------------------------------------------------------------
// TF32 helpers
// ---------------------------------------------------------------------------
__device__ __forceinline__ uint32_t f2tf32(float x) {
    uint32_t y;
    asm("cvt.rna.tf32.f32 %0, %1;" : "=r"(y) : "f"(x));
    return y;
}

__device__ __forceinline__ void mma_tf32(float& c0, float& c1, float& c2, float& c3,
                                         uint32_t a0, uint32_t a1, uint32_t a2, uint32_t a3,
                                         uint32_t b0, uint32_t b1) {
    asm volatile(
        "mma.sync.aligned.m16n8k8.row.col.f32.tf32.tf32.f32 "
        "{%0,%1,%2,%3}, {%4,%5,%6,%7}, {%8,%9}, {%0,%1,%2,%3};\n"
        : "+f"(c0), "+f"(c1), "+f"(c2), "+f"(c3)
        : "r"(a0), "r"(a1), "r"(a2), "r"(a3), "r"(b0), "r"(b1));
}

// ---------------------------------------------------------------------------
// K1: proj = hidden (4096x2048) @ W (2048x12320), TF32 tensor-core GEMM
//     BM=128 BN=128 BK=32, 256 threads, 2x4 warp grid, 64x32 per warp
// ---------------------------------------------------------------------------
__global__ __launch_bounds__(256) void gemm_tf32_kernel(
    const float* __restrict__ A, const float* __restrict__ B) {
    const int M_STRIDE = D_MODEL;   // A row stride (K)
    const int N = NPROJ;
    const int K = D_MODEL;

    __shared__ uint32_t As[128][36];   // 32 + 4 pad
    __shared__ uint32_t Bs[32][136];   // 128 + 8 pad

    int tid  = threadIdx.x;
    int bm   = blockIdx.y;
    int bn   = blockIdx.x;
    int warp = tid >> 5, lane = tid & 31;
    int wm = warp >> 2, wn = warp & 3;         // 2 x 4 warps
    int g  = lane >> 2, tig = lane & 3;

    float c[4][4][4];
    #pragma unroll
    for (int mi = 0; mi < 4; mi++)
        #pragma unroll
        for (int ni = 0; ni < 4; ni++)
            #pragma unroll
            for (int e = 0; e < 4; e++) c[mi][ni][e] = 0.f;

    for (int k0 = 0; k0 < K; k0 += 32) {
        // Load A tile 128x32 (always in range)
        #pragma unroll
        for (int i = 0; i < 4; i++) {
            int idx = i * 256 + tid;
            int r = idx >> 3, c4 = idx & 7;
            float4 v = *(const float4*)&A[(size_t)(bm * 128 + r) * M_STRIDE + k0 + c4 * 4];
            As[r][c4 * 4 + 0] = f2tf32(v.x);
            As[r][c4 * 4 + 1] = f2tf32(v.y);
            As[r][c4 * 4 + 2] = f2tf32(v.z);
            As[r][c4 * 4 + 3] = f2tf32(v.w);
        }
        // Load B tile 32x128 with N-tail predication
        #pragma unroll
        for (int i = 0; i < 4; i++) {
            int idx = i * 256 + tid;
            int r = idx >> 5, c4 = idx & 31;
            int col = bn * 128 + c4 * 4;
            float4 v = make_float4(0.f, 0.f, 0.f, 0.f);
            if (col < N) v = *(const float4*)&B[(size_t)(k0 + r) * N + col];
            Bs[r][c4 * 4 + 0] = f2tf32(v.x);
            Bs[r][c4 * 4 + 1] = f2tf32(v.y);
            Bs[r][c4 * 4 + 2] = f2tf32(v.z);
            Bs[r][c4 * 4 + 3] = f2tf32(v.w);
        }
        __syncthreads();

        #pragma unroll
        for (int kk = 0; kk < 4; kk++) {
            uint32_t af[4][4], bf[4][2];
            #pragma unroll
            for (int mi = 0; mi < 4; mi++) {
                int rb = wm * 64 + mi * 16;
                af[mi][0] = As[rb + g    ][kk * 8 + tig    ];
                af[mi][1] = As[rb + g + 8][kk * 8 + tig    ];
                af[mi][2] = As[rb + g    ][kk * 8 + tig + 4];
                af[mi][3] = As[rb + g + 8][kk * 8 + tig + 4];
            }
            #pragma unroll
            for (int ni = 0; ni < 4; ni++) {
                int cb = wn * 32 + ni * 8;
                bf[ni][0] = Bs[kk * 8 + tig    ][cb + g];
                bf[ni][1] = Bs[kk * 8 + tig + 4][cb + g];
            }
            #pragma unroll
            for (int mi = 0; mi < 4; mi++)
                #pragma unroll
                for (int ni = 0; ni < 4; ni++)
                    mma_tf32(c[mi][ni][0], c[mi][ni][1], c[mi][ni][2], c[mi][ni][3],
                             af[mi][0], af[mi][1], af[mi][2], af[mi][3],
                             bf[ni][0], bf[ni][1]);
        }
        __syncthreads();
    }

    // Epilogue
    #pragma unroll
    for (int mi = 0; mi < 4; mi++) {
        int row = bm * 128 + wm * 64 + mi * 16 + g;
        #pragma unroll
        for (int ni = 0; ni < 4; ni++) {
            int col = bn * 128 + wn * 32 + ni * 8 + tig * 2;
            if (col < N) {   // col even, N even -> col+1 also in range
                g_proj[(size_t)row * N + col    ] = c[mi][ni][0];
                g_proj[(size_t)row * N + col + 1] = c[mi][ni][1];
                g_proj[(size_t)(row + 8) * N + col    ] = c[mi][ni][2];
                g_proj[(size_t)(row + 8) * N + col + 1] = c[mi][ni][3];
            }
        }
    }
}

// ---------------------------------------------------------------------------
// K2: causal depthwise conv (width 4) + SiLU over first 8192 proj channels
// ---------------------------------------------------------------------------
__global__ __launch_bounds__(256) void conv_silu_kernel(const float* __restrict__ Wconv) {
    size_t idx = (size_t)blockIdx.x * 256 + threadIdx.x;   // < 4096*8192
    int c = (int)(idx & (CONV_CH - 1));
    int r = (int)(idx >> 13);
    int l = r & (SEQ - 1);

    float4 w = *(const float4*)&Wconv[c * 4];   // W[c][0..3]
    const float* xp = g_proj + (size_t)r * NPROJ + c;

    float acc = xp[0] * w.w;                                     // x[l]   * W[c,3]
    if (l >= 1) acc += xp[-(ptrdiff_t)NPROJ    ] * w.z;          // x[l-1] * W[c,2]
    if (l >= 2) acc += xp[-(ptrdiff_t)NPROJ * 2] * w.y;          // x[l-2] * W[c,1]
    if (l >= 3) acc += xp[-(ptrdiff_t)NPROJ * 3] * w.x;          // x[l-3] * W[c,0]

    float y = acc / (1.f + __expf(-acc));   // silu

    if (c < KEY_DIM)           g_qb[(size_t)r * KEY_DIM + c] = y;
    else if (c < 2 * KEY_DIM)  g_kb[(size_t)r * KEY_DIM + (c - KEY_DIM)] = y;
    else                       g_vb[(size_t)r * VALUE_DIM + (c - 2 * KEY_DIM)] = y;
}

// ---------------------------------------------------------------------------
// K3: per-head l2norm of q and k (in place)
// ---------------------------------------------------------------------------
__global__ __launch_bounds__(128) void l2norm_kernel() {
    int r  = blockIdx.x >> 5;
    int hh = blockIdx.x & 31;
    float* buf = (hh < 16) ? g_qb : g_kb;
    int head = hh & 15;
    int tid = threadIdx.x, lane = tid & 31, warp = tid >> 5;

    float* p = buf + (size_t)r * KEY_DIM + head * D_HEAD + tid;
    float v = *p;
    float ss = v * v;
    #pragma unroll
    for (int off = 16; off > 0; off >>= 1) ss += __shfl_xor_sync(0xffffffffu, ss, off);

    __shared__ float red[4];
    if (lane == 0) red[warp] = ss;
    __syncthreads();
    float total = red[0] + red[1] + red[2] + red[3];
    *p = v * rsqrtf(total + 1e-6f);
}

// ---------------------------------------------------------------------------
// K3b: eg = exp(-exp(A_log)*softplus(A+dt_bias)); beta = sigmoid(b)
// ---------------------------------------------------------------------------
__global__ __launch_bounds__(256) void gate_prep_kernel(
    const float* __restrict__ A_log, const float* __restrict__ dt_bias) {
    int idx = blockIdx.x * 256 + threadIdx.x;   // < 4096*16
    int r = idx >> 4, h = idx & 15;
    float Aval = g_proj[(size_t)r * NPROJ + ACOL_OFF + h];
    float bval = g_proj[(size_t)r * NPROJ + BCOL_OFF + h];
    float x = Aval + dt_bias[h];
    float sp = (x > 20.f) ? x : log1pf(expf(x));
    float gg = -expf(A_log[h]) * sp;
    g_eg[idx]   = expf(gg);
    g_beta[idx] = 1.f / (1.f + expf(-bval));
}

// ---------------------------------------------------------------------------
// K4: gated delta-rule scan.
// Grid = 128 blocks: (b, h, v-chunk of 64). 256 threads: warp covers 8
// columns x 4 k-segments (32 each). S lives in registers (32/thread).
// ---------------------------------------------------------------------------
__global__ __launch_bounds__(256, 1) void scan_kernel(float* __restrict__ out) {
    int bx = blockIdx.x;
    int b  = bx >> 6;
    int h  = (bx >> 2) & 15;
    int vc = bx & 3;
    int tid = threadIdx.x, lane = tid & 31, warp = tid >> 5;
    int seg  = lane & 3;               // k segment (32 values)
    int vloc = warp * 8 + (lane >> 2); // column within 64-chunk

    __shared__ float ks[4 * 36];   // padded stride 36 -> conflict-free LDS.128
    __shared__ float qs[4 * 36];
    __shared__ float vs[64];
    __shared__ float gs[64];
    __shared__ float s_eg, s_be;

    float S[32];
    #pragma unroll
    for (int i = 0; i < 32; i++) S[i] = 0.f;

    const float* kptr = g_kb + (size_t)b * SEQ * KEY_DIM + h * D_HEAD;
    const float* qptr = g_qb + (size_t)b * SEQ * KEY_DIM + h * D_HEAD;
    const float* vptr = g_vb + (size_t)b * SEQ * VALUE_DIM + h * HEAD_V + vc * 64;
    const float* gptr = g_proj + (size_t)b * SEQ * NPROJ + GATE_OFF + h * HEAD_V + vc * 64;
    const float* egp  = g_eg   + (size_t)b * SEQ * N_HEADS + h;
    const float* bep  = g_beta + (size_t)b * SEQ * N_HEADS + h;
    float* outp = out + ((size_t)b * SEQ * N_HEADS + h) * HEAD_V + vc * 64;

    // prefetch l = 0
    float pk = 0.f, pq = 0.f, pvx = 0.f, pg = 0.f, peg = 0.f, pbe = 0.f;
    if (tid < 128) pk = kptr[tid];
    else           pq = qptr[tid - 128];
    if (tid < 64)               pvx = vptr[tid];
    else if (tid < 128)         pg  = gptr[tid - 64];
    if (tid == 0) { peg = egp[0]; pbe = bep[0]; }

    const float scale = 0.08838834764831845f;   // 128^-0.5

    for (int l = 0; l < SEQ; l++) {
        __syncthreads();   // previous step finished reading shared
        if (tid < 128) ks[(tid >> 5) * 36 + (tid & 31)] = pk;
        else           qs[((tid - 128) >> 5) * 36 + (tid & 31)] = pq;
        if (tid < 64)          vs[tid] = pvx;
        else if (tid < 128)    gs[tid - 64] = pg;
        if (tid == 0) { s_eg = peg; s_be = pbe; }
        __syncthreads();

        // prefetch next step (hidden under compute)
        if (l + 1 < SEQ) {
            if (tid < 128) pk = kptr[(size_t)(l + 1) * KEY_DIM + tid];
            else           pq = qptr[(size_t)(l + 1) * KEY_DIM + (tid - 128)];
            if (tid < 64)            pvx = vptr[(size_t)(l + 1) * VALUE_DIM + tid];
            else if (tid < 128)      pg  = gptr[(size_t)(l + 1) * NPROJ + (tid - 64)];
            if (tid == 0) { peg = egp[(size_t)(l + 1) * N_HEADS]; pbe = bep[(size_t)(l + 1) * N_HEADS]; }
        }

        float4 kf[8], qf[8];
        const float4* ks4 = (const float4*)&ks[seg * 36];
        const float4* qs4 = (const float4*)&qs[seg * 36];
        #pragma unroll
        for (int i = 0; i < 8; i++) { kf[i] = ks4[i]; qf[i] = qs4[i]; }

        float eg = s_eg, be = s_be;

        // kS partial (pre-decay; eg factors out)
        float fp = 0.f;
        #pragma unroll
        for (int i = 0; i < 8; i++) {
            fp = fmaf(kf[i].x, S[4 * i + 0], fp);
            fp = fmaf(kf[i].y, S[4 * i + 1], fp);
            fp = fmaf(kf[i].z, S[4 * i + 2], fp);
            fp = fmaf(kf[i].w, S[4 * i + 3], fp);
        }
        fp += __shfl_xor_sync(0xffffffffu, fp, 1);
        fp += __shfl_xor_sync(0xffffffffu, fp, 2);

        float vval  = vs[vloc];
        float delta = (vval - eg * fp) * be;

        // state update + output accumulation
        float o = 0.f;
        #pragma unroll
        for (int i = 0; i < 8; i++) {
            S[4 * i + 0] = fmaf(S[4 * i + 0], eg, kf[i].x * delta);
            o = fmaf(qf[i].x, S[4 * i + 0], o);
            S[4 * i + 1] = fmaf(S[4 * i + 1], eg, kf[i].y * delta);
            o = fmaf(qf[i].y, S[4 * i + 1], o);
            S[4 * i + 2] = fmaf(S[4 * i + 2], eg, kf[i].z * delta);
            o = fmaf(qf[i].z, S[4 * i + 2], o);
            S[4 * i + 3] = fmaf(S[4 * i + 3], eg, kf[i].w * delta);
            o = fmaf(qf[i].w, S[4 * i + 3], o);
        }
        o += __shfl_xor_sync(0xffffffffu, o, 1);
        o += __shfl_xor_sync(0xffffffffu, o, 2);

        if (seg == 0) {
            float gv = gs[vloc];
            float silu_g = gv / (1.f + __expf(-gv));
            outp[(size_t)l * (N_HEADS * HEAD_V) + vloc] = o * scale * silu_g;
        }
    }
}

// ---------------------------------------------------------------------------
// Launch
// ---------------------------------------------------------------------------
extern "C" void kernel_launch(void* const* d_in, const int* in_sizes, int n_in,
                              void* d_out, int out_size) {
    const float* hidden  = (const float*)d_in[0];   // (2,2048,2048)
    const float* W       = (const float*)d_in[1];   // (2048,12320)
    const float* Wconv   = (const float*)d_in[2];   // (8192,4)
    const float* A_log   = (const float*)d_in[3];   // (16)
    const float* dt_bias = (const float*)d_in[4];   // (16)
    float* out = (float*)d_out;

    // K1: projection GEMM
    {
        dim3 grid((NPROJ + 127) / 128, MROWS / 128);   // 97 x 32
        gemm_tf32_kernel<<<grid, 256>>>(hidden, W);
    }
    // K2: conv + silu
    {
        size_t total = (size_t)MROWS * CONV_CH;        // 33.5M
        conv_silu_kernel<<<(unsigned)(total / 256), 256>>>(Wconv);
    }
    // K3b: eg / beta
    gate_prep_kernel<<<(MROWS * N_HEADS) / 256, 256>>>(A_log, dt_bias);
    // K3: l2norm q, k
    l2norm_kernel<<<MROWS * 32, 128>>>();
    // K4: scan + gating
    scan_kernel<<<128, 256>>>(out);
}

// round 6
// speedup vs baseline: 1.1171x; 1.1171x over previous
#include <cuda_runtime.h>
#include <cstdint>

// ---------------------------------------------------------------------------
// Problem constants
// ---------------------------------------------------------------------------
#define D_MODEL   2048
#define N_HEADS   16
#define D_HEAD    128
#define HEAD_V    256
#define KEY_DIM   2048
#define VALUE_DIM 4096
#define NPROJ     12320     // 2*KEY_DIM + 2*VALUE_DIM + 2*N_HEADS
#define NPROJ_PAD 12416     // 97 * 128
#define CONV_CH   8192      // 2*KEY_DIM + VALUE_DIM
#define BATCH     2
#define SEQ       2048
#define MROWS     (BATCH*SEQ)          // 4096
#define GATE_OFF  8192
#define BCOL_OFF  12288
#define ACOL_OFF  12304

// ---------------------------------------------------------------------------
// Scratch (static device globals -- no allocation allowed)
// ---------------------------------------------------------------------------
__device__ float g_proj[(size_t)MROWS * NPROJ];       // 4096 x 12320
__device__ float g_at[(size_t)MROWS * D_MODEL];       // A, tf32, k-permuted
__device__ float g_bt[(size_t)NPROJ_PAD * D_MODEL];   // B^T, tf32, k-permuted
__device__ float g_qb[(size_t)MROWS * KEY_DIM];
__device__ float g_kb[(size_t)MROWS * KEY_DIM];
__device__ float g_vb[(size_t)MROWS * VALUE_DIM];
__device__ float g_eg[(size_t)MROWS * N_HEADS];
__device__ float g_beta[(size_t)MROWS * N_HEADS];

// ---------------------------------------------------------------------------
// Helpers
// ---------------------------------------------------------------------------
__device__ __forceinline__ uint32_t smem_to_u32(const void* p) {
    uint32_t a;
    asm("{ .reg .u64 t; cvta.to.shared.u64 t, %1; cvt.u32.u64 %0, t; }" : "=r"(a) : "l"(p));
    return a;
}
__device__ __forceinline__ uint32_t f2tf32(float x) {
    uint32_t y;
    asm("cvt.rna.tf32.f32 %0, %1;" : "=r"(y) : "f"(x));
    return y;
}
__device__ __forceinline__ void mma_tf32(float& c0, float& c1, float& c2, float& c3,
                                         float a0, float a1, float a2, float a3,
                                         float b0, float b1) {
    asm volatile(
        "mma.sync.aligned.m16n8k8.row.col.f32.tf32.tf32.f32 "
        "{%0,%1,%2,%3}, {%4,%5,%6,%7}, {%8,%9}, {%0,%1,%2,%3};\n"
        : "+f"(c0), "+f"(c1), "+f"(c2), "+f"(c3)
        : "r"(__float_as_uint(a0)), "r"(__float_as_uint(a1)),
          "r"(__float_as_uint(a2)), "r"(__float_as_uint(a3)),
          "r"(__float_as_uint(b0)), "r"(__float_as_uint(b1)));
}

// ---------------------------------------------------------------------------
// P1: A (4096x2048) -> g_at: tf32, per-32-block k-permutation
//     k' = (k&3)*8 + ((k>>2)&7)
// ---------------------------------------------------------------------------
__global__ __launch_bounds__(256) void prep_a_kernel(const float* __restrict__ A) {
    int id = blockIdx.x * 256 + threadIdx.x;     // < 4096*2048
    int k = id & 2047;
    int kp = (k & ~31) | (((k & 3) << 3) | ((k >> 2) & 7));
    g_at[(size_t)(id >> 11) * 2048 + kp] = __uint_as_float(f2tf32(A[id]));
}

// ---------------------------------------------------------------------------
// P2: B (2048 x 12320) -> g_bt (12416 x 2048): transpose + tf32 + k-perm
// ---------------------------------------------------------------------------
__global__ __launch_bounds__(256) void prep_b_kernel(const float* __restrict__ B) {
    __shared__ float t[32][33];
    int nt = blockIdx.x, kt = blockIdx.y;        // 385 x 64
    int tx = threadIdx.x & 31, ty = threadIdx.x >> 5;   // ty 0..7
    #pragma unroll
    for (int i = 0; i < 4; i++) {
        int k = kt * 32 + ty + i * 8;
        t[ty + i * 8][tx] = B[(size_t)k * NPROJ + nt * 32 + tx];
    }
    __syncthreads();
    int kp = ((tx & 3) << 3) | ((tx >> 2) & 7);
    #pragma unroll
    for (int i = 0; i < 4; i++) {
        int n = nt * 32 + ty + i * 8;
        g_bt[(size_t)n * 2048 + kt * 32 + kp] = __uint_as_float(f2tf32(t[tx][ty + i * 8]));
    }
}

// P2b: zero padding rows 12320..12415 of g_bt (determinism: never read garbage)
__global__ __launch_bounds__(256) void prep_b_tail_kernel() {
    size_t id = (size_t)blockIdx.x * 256 + threadIdx.x;  // < 96*2048
    g_bt[(size_t)NPROJ * D_MODEL + id] = 0.f;
}

// ---------------------------------------------------------------------------
// K1: proj = A @ B, tf32 mma.sync, CTA tile 256x128, BK=32,
//     cp.async(8B) double buffer, conflict-free 8B swizzle, warp tile 64x64
// ---------------------------------------------------------------------------
#define GSM_TOTAL 98304   // A: 2 x 32KB, B: 2 x 16KB

__global__ __launch_bounds__(256, 1) void gemm_kernel() {
    extern __shared__ float smem[];
    uint32_t sb = smem_to_u32(smem);
    int tid = threadIdx.x;
    int bm = blockIdx.x, bn = blockIdx.y;
    int warp = tid >> 5, lane = tid & 31;
    int wm = warp >> 1, wn = warp & 1;          // 4 x 2 warp grid
    int g = lane >> 2, tig = lane & 3;

    // cp.async bases: piece p = tid&15 (8B pieces), start row r0 = tid>>4
    int p0 = tid & 15, r0 = tid >> 4;
    int swp = ((p0 + 3 * (r0 & 15)) & 15);
    const float* srcA0 = g_at + (size_t)(bm * 256 + r0) * 2048 + p0 * 2;
    const float* srcB0 = g_bt + (size_t)(bn * 128 + r0) * 2048 + p0 * 2;
    uint32_t dstA0 = sb + (uint32_t)(r0 * 128 + swp * 8);
    uint32_t dstB0 = sb + 65536u + (uint32_t)(r0 * 128 + swp * 8);

    #define GEMM_ISSUE(bufsel, it) do { \
        uint32_t _da = dstA0 + (uint32_t)(bufsel) * 32768u; \
        const float* _sa = srcA0 + (size_t)(it) * 32; \
        _Pragma("unroll") \
        for (int _j = 0; _j < 16; _j++) \
            asm volatile("cp.async.ca.shared.global [%0], [%1], 8;" \
                :: "r"(_da + _j * 2048u), "l"(_sa + (size_t)_j * 16 * 2048)); \
        uint32_t _db = dstB0 + (uint32_t)(bufsel) * 16384u; \
        const float* _sb = srcB0 + (size_t)(it) * 32; \
        _Pragma("unroll") \
        for (int _j = 0; _j < 8; _j++) \
            asm volatile("cp.async.ca.shared.global [%0], [%1], 8;" \
                :: "r"(_db + _j * 2048u), "l"(_sb + (size_t)_j * 16 * 2048)); \
        asm volatile("cp.async.commit_group;"); \
    } while (0)

    float c[4][8][4];
    #pragma unroll
    for (int mi = 0; mi < 4; mi++)
        #pragma unroll
        for (int ni = 0; ni < 8; ni++)
            #pragma unroll
            for (int e = 0; e < 4; e++) c[mi][ni][e] = 0.f;

    // fragment-address constants (in float2 units; row stride = 16 float2)
    int cLo = (4 * tig + 3 * g) & 15;            // rows with (row&15) == g
    int cHi = (4 * tig + 3 * (g + 8)) & 15;      // rows with (row&15) == g+8

    GEMM_ISSUE(0, 0);

    for (int it = 0; it < 64; it++) {
        if (it + 1 < 64) {
            GEMM_ISSUE((it + 1) & 1, it + 1);
            asm volatile("cp.async.wait_group 1;" ::: "memory");
        } else {
            asm volatile("cp.async.wait_group 0;" ::: "memory");
        }
        __syncthreads();

        const float2* A2 = (const float2*)smem + (it & 1) * 4096;
        const float2* B2 = (const float2*)smem + 8192 + (it & 1) * 2048;

        #pragma unroll
        for (int kk = 0; kk < 4; kk++) {
            float2 alo[4], ahi[4], bf[8];
            int oLo = (cLo + kk) & 15, oHi = (cHi + kk) & 15;
            #pragma unroll
            for (int mi = 0; mi < 4; mi++) {
                int rb = (wm * 64 + mi * 16 + g) * 16;
                alo[mi] = A2[rb + oLo];
                ahi[mi] = A2[rb + 128 + oHi];
            }
            #pragma unroll
            for (int ni = 0; ni < 8; ni++) {
                int nb = (wn * 64 + ni * 8 + g) * 16;
                bf[ni] = B2[nb + ((ni & 1) ? oHi : oLo)];
            }
            #pragma unroll
            for (int mi = 0; mi < 4; mi++)
                #pragma unroll
                for (int ni = 0; ni < 8; ni++)
                    mma_tf32(c[mi][ni][0], c[mi][ni][1], c[mi][ni][2], c[mi][ni][3],
                             alo[mi].x, ahi[mi].x, alo[mi].y, ahi[mi].y,
                             bf[ni].x, bf[ni].y);
        }
        __syncthreads();
    }

    // Epilogue
    #pragma unroll
    for (int mi = 0; mi < 4; mi++) {
        int row = bm * 256 + wm * 64 + mi * 16 + g;
        #pragma unroll
        for (int ni = 0; ni < 8; ni++) {
            int col = bn * 128 + wn * 64 + ni * 8 + tig * 2;
            if (col < NPROJ) {
                float2 v0 = make_float2(c[mi][ni][0], c[mi][ni][1]);
                float2 v1 = make_float2(c[mi][ni][2], c[mi][ni][3]);
                *(float2*)&g_proj[(size_t)row * NPROJ + col] = v0;
                *(float2*)&g_proj[(size_t)(row + 8) * NPROJ + col] = v1;
            }
        }
    }
}

// ---------------------------------------------------------------------------
// K2: causal depthwise conv (width 4) + SiLU over first 8192 proj channels
// ---------------------------------------------------------------------------
__global__ __launch_bounds__(256) void conv_silu_kernel(const float* __restrict__ Wconv) {
    size_t idx = (size_t)blockIdx.x * 256 + threadIdx.x;
    int c = (int)(idx & (CONV_CH - 1));
    int r = (int)(idx >> 13);
    int l = r & (SEQ - 1);

    float4 w = *(const float4*)&Wconv[c * 4];
    const float* xp = g_proj + (size_t)r * NPROJ + c;

    float acc = xp[0] * w.w;
    if (l >= 1) acc += xp[-(ptrdiff_t)NPROJ    ] * w.z;
    if (l >= 2) acc += xp[-(ptrdiff_t)NPROJ * 2] * w.y;
    if (l >= 3) acc += xp[-(ptrdiff_t)NPROJ * 3] * w.x;

    float y = acc / (1.f + __expf(-acc));

    if (c < KEY_DIM)           g_qb[(size_t)r * KEY_DIM + c] = y;
    else if (c < 2 * KEY_DIM)  g_kb[(size_t)r * KEY_DIM + (c - KEY_DIM)] = y;
    else                       g_vb[(size_t)r * VALUE_DIM + (c - 2 * KEY_DIM)] = y;
}

// ---------------------------------------------------------------------------
// K3: per-head l2norm of q and k (warp per head-row)
// ---------------------------------------------------------------------------
__global__ __launch_bounds__(256) void l2norm_kernel() {
    int gid  = blockIdx.x * 8 + (threadIdx.x >> 5);   // warp id: r*32 + hh
    int lane = threadIdx.x & 31;
    int r  = gid >> 5;
    int hh = gid & 31;
    float* buf = (hh < 16) ? g_qb : g_kb;
    float* p = buf + (size_t)r * KEY_DIM + (hh & 15) * D_HEAD + lane * 4;
    float4 v = *(const float4*)p;
    float ss = v.x * v.x + v.y * v.y + v.z * v.z + v.w * v.w;
    #pragma unroll
    for (int off = 16; off > 0; off >>= 1) ss += __shfl_xor_sync(0xffffffffu, ss, off);
    float inv = rsqrtf(ss + 1e-6f);
    v.x *= inv; v.y *= inv; v.z *= inv; v.w *= inv;
    *(float4*)p = v;
}

// ---------------------------------------------------------------------------
// K3b: eg = exp(-exp(A_log)*softplus(A+dt_bias)); beta = sigmoid(b)
// ---------------------------------------------------------------------------
__global__ __launch_bounds__(256) void gate_prep_kernel(
    const float* __restrict__ A_log, const float* __restrict__ dt_bias) {
    int idx = blockIdx.x * 256 + threadIdx.x;
    int r = idx >> 4, h = idx & 15;
    float Aval = g_proj[(size_t)r * NPROJ + ACOL_OFF + h];
    float bval = g_proj[(size_t)r * NPROJ + BCOL_OFF + h];
    float x = Aval + dt_bias[h];
    float sp = (x > 20.f) ? x : log1pf(expf(x));
    float gg = -expf(A_log[h]) * sp;
    g_eg[idx]   = expf(gg);
    g_beta[idx] = 1.f / (1.f + expf(-bval));
}

// ---------------------------------------------------------------------------
// K4: gated delta-rule scan (unchanged, passing)
// ---------------------------------------------------------------------------
__global__ __launch_bounds__(256, 1) void scan_kernel(float* __restrict__ out) {
    int bx = blockIdx.x;
    int b  = bx >> 6;
    int h  = (bx >> 2) & 15;
    int vc = bx & 3;
    int tid = threadIdx.x, lane = tid & 31, warp = tid >> 5;
    int seg  = lane & 3;
    int vloc = warp * 8 + (lane >> 2);

    __shared__ float ks[4 * 36];
    __shared__ float qs[4 * 36];
    __shared__ float vs[64];
    __shared__ float gs[64];
    __shared__ float s_eg, s_be;

    float S[32];
    #pragma unroll
    for (int i = 0; i < 32; i++) S[i] = 0.f;

    const float* kptr = g_kb + (size_t)b * SEQ * KEY_DIM + h * D_HEAD;
    const float* qptr = g_qb + (size_t)b * SEQ * KEY_DIM + h * D_HEAD;
    const float* vptr = g_vb + (size_t)b * SEQ * VALUE_DIM + h * HEAD_V + vc * 64;
    const float* gptr = g_proj + (size_t)b * SEQ * NPROJ + GATE_OFF + h * HEAD_V + vc * 64;
    const float* egp  = g_eg   + (size_t)b * SEQ * N_HEADS + h;
    const float* bep  = g_beta + (size_t)b * SEQ * N_HEADS + h;
    float* outp = out + ((size_t)b * SEQ * N_HEADS + h) * HEAD_V + vc * 64;

    float pk = 0.f, pq = 0.f, pvx = 0.f, pg = 0.f, peg = 0.f, pbe = 0.f;
    if (tid < 128) pk = kptr[tid];
    else           pq = qptr[tid - 128];
    if (tid < 64)               pvx = vptr[tid];
    else if (tid < 128)         pg  = gptr[tid - 64];
    if (tid == 0) { peg = egp[0]; pbe = bep[0]; }

    const float scale = 0.08838834764831845f;   // 128^-0.5

    for (int l = 0; l < SEQ; l++) {
        __syncthreads();
        if (tid < 128) ks[(tid >> 5) * 36 + (tid & 31)] = pk;
        else           qs[((tid - 128) >> 5) * 36 + (tid & 31)] = pq;
        if (tid < 64)          vs[tid] = pvx;
        else if (tid < 128)    gs[tid - 64] = pg;
        if (tid == 0) { s_eg = peg; s_be = pbe; }
        __syncthreads();

        if (l + 1 < SEQ) {
            if (tid < 128) pk = kptr[(size_t)(l + 1) * KEY_DIM + tid];
            else           pq = qptr[(size_t)(l + 1) * KEY_DIM + (tid - 128)];
            if (tid < 64)            pvx = vptr[(size_t)(l + 1) * VALUE_DIM + tid];
            else if (tid < 128)      pg  = gptr[(size_t)(l + 1) * NPROJ + (tid - 64)];
            if (tid == 0) { peg = egp[(size_t)(l + 1) * N_HEADS]; pbe = bep[(size_t)(l + 1) * N_HEADS]; }
        }

        float4 kf[8], qf[8];
        const float4* ks4 = (const float4*)&ks[seg * 36];
        const float4* qs4 = (const float4*)&qs[seg * 36];
        #pragma unroll
        for (int i = 0; i < 8; i++) { kf[i] = ks4[i]; qf[i] = qs4[i]; }

        float eg = s_eg, be = s_be;

        float fp = 0.f;
        #pragma unroll
        for (int i = 0; i < 8; i++) {
            fp = fmaf(kf[i].x, S[4 * i + 0], fp);
            fp = fmaf(kf[i].y, S[4 * i + 1], fp);
            fp = fmaf(kf[i].z, S[4 * i + 2], fp);
            fp = fmaf(kf[i].w, S[4 * i + 3], fp);
        }
        fp += __shfl_xor_sync(0xffffffffu, fp, 1);
        fp += __shfl_xor_sync(0xffffffffu, fp, 2);

        float vval  = vs[vloc];
        float delta = (vval - eg * fp) * be;

        float o = 0.f;
        #pragma unroll
        for (int i = 0; i < 8; i++) {
            S[4 * i + 0] = fmaf(S[4 * i + 0], eg, kf[i].x * delta);
            o = fmaf(qf[i].x, S[4 * i + 0], o);
            S[4 * i + 1] = fmaf(S[4 * i + 1], eg, kf[i].y * delta);
            o = fmaf(qf[i].y, S[4 * i + 1], o);
            S[4 * i + 2] = fmaf(S[4 * i + 2], eg, kf[i].z * delta);
            o = fmaf(qf[i].z, S[4 * i + 2], o);
            S[4 * i + 3] = fmaf(S[4 * i + 3], eg, kf[i].w * delta);
            o = fmaf(qf[i].w, S[4 * i + 3], o);
        }
        o += __shfl_xor_sync(0xffffffffu, o, 1);
        o += __shfl_xor_sync(0xffffffffu, o, 2);

        if (seg == 0) {
            float gv = gs[vloc];
            float silu_g = gv / (1.f + __expf(-gv));
            outp[(size_t)l * (N_HEADS * HEAD_V) + vloc] = o * scale * silu_g;
        }
    }
}

// ---------------------------------------------------------------------------
// Launch
// ---------------------------------------------------------------------------
extern "C" void kernel_launch(void* const* d_in, const int* in_sizes, int n_in,
                              void* d_out, int out_size) {
    const float* hidden  = (const float*)d_in[0];
    const float* W       = (const float*)d_in[1];
    const float* Wconv   = (const float*)d_in[2];
    const float* A_log   = (const float*)d_in[3];
    const float* dt_bias = (const float*)d_in[4];
    float* out = (float*)d_out;

    // P1/P2: tf32 convert + layout
    prep_a_kernel<<<(MROWS * D_MODEL) / 256, 256>>>(hidden);
    {
        dim3 grid(NPROJ / 32, D_MODEL / 32);   // 385 x 64
        prep_b_kernel<<<grid, 256>>>(W);
    }
    prep_b_tail_kernel<<<(96 * D_MODEL) / 256, 256>>>();
    // K1: GEMM
    cudaFuncSetAttribute(gemm_kernel, cudaFuncAttributeMaxDynamicSharedMemorySize, GSM_TOTAL);
    {
        dim3 grid(MROWS / 256, NPROJ_PAD / 128);   // 16 x 97
        gemm_kernel<<<grid, 256, GSM_TOTAL>>>();
    }
    // K2: conv + silu
    {
        size_t total = (size_t)MROWS * CONV_CH;
        conv_silu_kernel<<<(unsigned)(total / 256), 256>>>(Wconv);
    }
    // K3b: eg / beta
    gate_prep_kernel<<<(MROWS * N_HEADS) / 256, 256>>>(A_log, dt_bias);
    // K3: l2norm q, k
    l2norm_kernel<<<(MROWS * 32) / 8, 256>>>();
    // K4: scan + gating
    scan_kernel<<<128, 256>>>(out);
}